// round 12
// baseline (speedup 1.0000x reference)
#include <cuda_runtime.h>
#include <cuda_fp16.h>
#include <cuda_fp8.h>
#include <cstdint>

#define KDIM 4096
#define MDIM 8192
#define NDIM 4096
#define NGRP 128              // K / 32 groups per row

#define BM 128
#define BN 128
#define BK 64                 // 2 groups per mainloop iter
#define STAGES 4
#define KSTEPS (KDIM / BK)    // 64
#define SA_OFF 32768
#define SB_OFF 33792
#define STAGE_BYTES 34816
#define SMEM_TOTAL (STAGES * STAGE_BYTES)

// Quantized operands (e4m3 values stored exactly as fp16) + per-group scales
__device__ __align__(1024) __half g_qA[(size_t)MDIM * KDIM];   // 64 MB
__device__ __align__(1024) __half g_qB[(size_t)NDIM * KDIM];   // 32 MB
__device__ __align__(1024) float  g_sA[(size_t)MDIM * NGRP];   //  4 MB
__device__ __align__(1024) float  g_sB[(size_t)NDIM * NGRP];   //  2 MB

// ---------------------------------------------------------------------------
// PTX helpers
// ---------------------------------------------------------------------------
__device__ __forceinline__ uint32_t s2u(const void* p) {
    return (uint32_t)__cvta_generic_to_shared(p);
}
__device__ __forceinline__ void cp16(uint32_t s, const void* g) {
    asm volatile("cp.async.cg.shared.global [%0], [%1], 16;" :: "r"(s), "l"(g) : "memory");
}
__device__ __forceinline__ void cp8(uint32_t s, const void* g) {
    asm volatile("cp.async.ca.shared.global [%0], [%1], 8;" :: "r"(s), "l"(g) : "memory");
}
__device__ __forceinline__ void cp_commit() {
    asm volatile("cp.async.commit_group;" ::: "memory");
}
__device__ __forceinline__ void cp_wait2() {
    asm volatile("cp.async.wait_group 2;" ::: "memory");
}
__device__ __forceinline__ void ldsm4(uint32_t* r, uint32_t addr) {
    asm volatile("ldmatrix.sync.aligned.m8n8.x4.shared.b16 {%0,%1,%2,%3}, [%4];"
                 : "=r"(r[0]), "=r"(r[1]), "=r"(r[2]), "=r"(r[3]) : "r"(addr));
}
__device__ __forceinline__ void mma16816(float* d, const uint32_t* a,
                                         const uint32_t* b, const float* c) {
    asm volatile(
        "mma.sync.aligned.m16n8k16.row.col.f32.f16.f16.f32 "
        "{%0,%1,%2,%3}, {%4,%5,%6,%7}, {%8,%9}, {%10,%11,%12,%13};"
        : "=f"(d[0]), "=f"(d[1]), "=f"(d[2]), "=f"(d[3])
        : "r"(a[0]), "r"(a[1]), "r"(a[2]), "r"(a[3]), "r"(b[0]), "r"(b[1]),
          "f"(c[0]), "f"(c[1]), "f"(c[2]), "f"(c[3]));
}
// Packed fp32x2 ops (sm_100+ base PTX; ALU-pipe pack, FMA-pipe math)
__device__ __forceinline__ uint64_t pack2(float lo, float hi) {
    uint64_t r;
    asm("mov.b64 %0, {%1, %2};" : "=l"(r) : "f"(lo), "f"(hi));
    return r;
}
__device__ __forceinline__ uint64_t mul2(uint64_t a, uint64_t b) {
    uint64_t d;
    asm("mul.rn.f32x2 %0, %1, %2;" : "=l"(d) : "l"(a), "l"(b));
    return d;
}
__device__ __forceinline__ uint64_t fma2(uint64_t a, uint64_t b, uint64_t c) {
    uint64_t d;
    asm("fma.rn.f32x2 %0, %1, %2, %3;" : "=l"(d) : "l"(a), "l"(b), "l"(c));
    return d;
}
__device__ __forceinline__ void unpack2(uint64_t v, float& lo, float& hi) {
    asm("mov.b64 {%0, %1}, %2;" : "=f"(lo), "=f"(hi) : "l"(v));
}

// ---------------------------------------------------------------------------
// Quantize: q = fp8_e4m3(v / scale) stored EXACTLY as fp16; scale stored fp32.
// dest flag selects device-global buffers IN DEVICE CODE (host symbol
// addresses are invalid device pointers).
// ---------------------------------------------------------------------------
__global__ void quant_kernel(const float* __restrict__ src, int dest) {
    __half* __restrict__ qdst = dest ? g_qB : g_qA;
    float*  __restrict__ sdst = dest ? g_sB : g_sA;

    long long t = (long long)blockIdx.x * blockDim.x + threadIdx.x;
    long long row = t >> 10;            // 1024 float4 per row
    int f4 = (int)(t & 1023);

    const float4 v4 = reinterpret_cast<const float4*>(src)[t];
    float a = fmaxf(fmaxf(fabsf(v4.x), fabsf(v4.y)),
                    fmaxf(fabsf(v4.z), fabsf(v4.w)));
    a = fmaxf(a, __shfl_xor_sync(0xffffffffu, a, 1));
    a = fmaxf(a, __shfl_xor_sync(0xffffffffu, a, 2));
    a = fmaxf(a, __shfl_xor_sync(0xffffffffu, a, 4));
    float scale = __fdiv_rn(fmaxf(a, 1e-8f), 448.0f);

    float vv[4] = {v4.x, v4.y, v4.z, v4.w};
    __half h[4];
#pragma unroll
    for (int i = 0; i < 4; i++) {
        float q = __fdiv_rn(vv[i], scale);
        __nv_fp8_e4m3 f8(q);                 // RNE, satfinite (matches reference)
        h[i] = __float2half((float)f8);      // exact: e4m3 subset of fp16
    }
    __half2 h01 = __halves2half2(h[0], h[1]);
    __half2 h23 = __halves2half2(h[2], h[3]);
    uint2 st;
    st.x = *reinterpret_cast<uint32_t*>(&h01);
    st.y = *reinterpret_cast<uint32_t*>(&h23);
    *reinterpret_cast<uint2*>(qdst + ((size_t)row << 12) + f4 * 4) = st;

    if ((f4 & 7) == 0)
        sdst[(size_t)row * NGRP + (f4 >> 3)] = scale;
}

// ---------------------------------------------------------------------------
// GEMM: out[M,N] = sum_g (qA_g . qB_g) * sA[m,g] * sB[n,g] + bias[n]
// 128x128 CTA tile, BK=64, 4-stage cp.async, 8 warps, warp tile 64x32.
// Rescale done with packed f32x2 mul/fma (half the fma-pipe issues).
// ---------------------------------------------------------------------------
__global__ void __launch_bounds__(256, 1)
gemm_kernel(const float* __restrict__ bias, float* __restrict__ out) {
    extern __shared__ __align__(1024) char smem_raw[];
    const uint32_t sbase = s2u(smem_raw);
    const int tid  = threadIdx.x;
    const int lane = tid & 31;
    const int warp = tid >> 5;
    const int warpM = warp & 1;          // 2 x 64 rows
    const int warpN = warp >> 1;         // 4 x 32 cols

    // Grid swizzle: 16-wide N super-columns
    const int gid = blockIdx.x;
    const int sc  = gid >> 10;
    const int rem = gid & 1023;
    const int blockN = ((sc << 4) | (rem & 15)) * BN;
    const int blockM = (rem >> 4) * BM;

    // Precomputed ldmatrix lane addressing
    const int lx7   = lane & 7;
    const int aRowB = warpM * 64 + (lane & 15);
    const int aCl   = lane >> 4;
    const int bRowB = warpN * 32 + ((lane >> 4) << 3) + (lane & 7);
    const int bCl   = (lane >> 3) & 1;
    const int rsIdx = warpM * 64 + (lane >> 2);
    const int csIdx = warpN * 32 + ((lane & 3) << 1);

    const __half* gA = g_qA + (size_t)blockM * KDIM;
    const __half* gB = g_qB + (size_t)blockN * KDIM;
    const float*  gsA = g_sA + (size_t)blockM * NGRP;
    const float*  gsB = g_sB + (size_t)blockN * NGRP;

    uint64_t acc2[32];                    // (i,j) -> {rows r / r+8} x (c,c+1)
#pragma unroll
    for (int i = 0; i < 32; i++) acc2[i] = 0ull;
    const float zf[4] = {0.f, 0.f, 0.f, 0.f};

    auto load_stage = [&](int stage, int kb) {
        uint32_t st = sbase + stage * STAGE_BYTES;
#pragma unroll
        for (int u = 0; u < 4; u++) {
            int idx = tid + u * 256;           // 0..1023 chunks
            int row = idx >> 3, c = idx & 7;
            cp16(st + row * 128 + (((c ^ (row & 7))) << 4),
                 gA + (size_t)row * KDIM + kb * 64 + c * 8);
        }
#pragma unroll
        for (int u = 0; u < 4; u++) {
            int idx = tid + u * 256;
            int row = idx >> 3, c = idx & 7;
            cp16(st + 16384 + row * 128 + (((c ^ (row & 7))) << 4),
                 gB + (size_t)row * KDIM + kb * 64 + c * 8);
        }
        if (tid < 128)
            cp8(st + SA_OFF + tid * 8, gsA + (size_t)tid * NGRP + kb * 2);
        else
            cp8(st + SB_OFF + (tid - 128) * 8,
                gsB + (size_t)(tid - 128) * NGRP + kb * 2);
    };

#pragma unroll
    for (int s = 0; s < 3; s++) { load_stage(s, s); cp_commit(); }

    for (int kb = 0; kb < KSTEPS; kb++) {
        cp_wait2();
        __syncthreads();
        const int stage = kb & 3;
        const uint32_t st = sbase + stage * STAGE_BYTES;
        const float2* sAf2 = reinterpret_cast<const float2*>(
            smem_raw + stage * STAGE_BYTES + SA_OFF);
        const float2* sBf2 = reinterpret_cast<const float2*>(
            smem_raw + stage * STAGE_BYTES + SB_OFF);

        float2 sLo[4], sHi[4], sC0[4], sC1[4];
#pragma unroll
        for (int i = 0; i < 4; i++) {
            sLo[i] = sAf2[rsIdx + i * 16];
            sHi[i] = sAf2[rsIdx + i * 16 + 8];
        }
#pragma unroll
        for (int j = 0; j < 4; j++) {
            sC0[j] = sBf2[csIdx + j * 8];
            sC1[j] = sBf2[csIdx + j * 8 + 1];
        }

#pragma unroll
        for (int g = 0; g < 2; g++) {
            uint32_t afr[2][4][4], bfr[2][2][4];
#pragma unroll
            for (int kh = 0; kh < 2; kh++) {
                const int kk = g * 2 + kh;
#pragma unroll
                for (int i = 0; i < 4; i++)
                    ldsm4(afr[kh][i],
                          st + (aRowB + i * 16) * 128 +
                              (((kk * 2 + aCl) ^ lx7) << 4));
#pragma unroll
                for (int jp = 0; jp < 2; jp++)
                    ldsm4(bfr[kh][jp],
                          st + 16384 + (bRowB + jp * 16) * 128 +
                              (((kk * 2 + bCl) ^ lx7) << 4));
            }
            // Packed scale pairs for this group (packs hit the ALU pipe)
            uint64_t rrLo[4], rrHi[4], cc[4];
#pragma unroll
            for (int i = 0; i < 4; i++) {
                const float rlo = g ? sLo[i].y : sLo[i].x;
                const float rhi = g ? sHi[i].y : sHi[i].x;
                rrLo[i] = pack2(rlo, rlo);
                rrHi[i] = pack2(rhi, rhi);
            }
#pragma unroll
            for (int j = 0; j < 4; j++)
                cc[j] = pack2(g ? sC0[j].y : sC0[j].x,
                              g ? sC1[j].y : sC1[j].x);
#pragma unroll
            for (int i = 0; i < 4; i++) {
#pragma unroll
                for (int j = 0; j < 4; j++) {
                    float t[4];
                    mma16816(t, afr[0][i], &bfr[0][j >> 1][(j & 1) * 2], zf);
                    mma16816(t, afr[1][i], &bfr[1][j >> 1][(j & 1) * 2], t);
                    const int idx = ((i << 2) + j) << 1;
                    uint64_t t01 = pack2(t[0], t[1]);
                    uint64_t t23 = pack2(t[2], t[3]);
                    acc2[idx + 0] = fma2(t01, mul2(rrLo[i], cc[j]), acc2[idx + 0]);
                    acc2[idx + 1] = fma2(t23, mul2(rrHi[i], cc[j]), acc2[idx + 1]);
                }
            }
        }
        if (kb < KSTEPS - 3) load_stage((kb + 3) & 3, kb + 3);
        cp_commit();   // uniform group count per iteration
    }

    // Epilogue: bias add + fp32 store
#pragma unroll
    for (int i = 0; i < 4; i++) {
        const int r0 = blockM + warpM * 64 + i * 16 + (lane >> 2);
#pragma unroll
        for (int j = 0; j < 4; j++) {
            const int c = blockN + warpN * 32 + j * 8 + ((lane & 3) << 1);
            const float2 bb = __ldg(reinterpret_cast<const float2*>(bias + c));
            const int idx = ((i << 2) + j) << 1;
            float a0, a1, a2, a3;
            unpack2(acc2[idx + 0], a0, a1);
            unpack2(acc2[idx + 1], a2, a3);
            float2 v0 = {a0 + bb.x, a1 + bb.y};
            float2 v1 = {a2 + bb.x, a3 + bb.y};
            *reinterpret_cast<float2*>(out + (size_t)r0 * NDIM + c) = v0;
            *reinterpret_cast<float2*>(out + (size_t)(r0 + 8) * NDIM + c) = v1;
        }
    }
}

// ---------------------------------------------------------------------------
extern "C" void kernel_launch(void* const* d_in, const int* in_sizes, int n_in,
                              void* d_out, int out_size) {
    const float* x    = (const float*)d_in[0];   // [4,2048,4096] fp32
    const float* W    = (const float*)d_in[1];   // [4096,4096]   fp32
    const float* bias = (const float*)d_in[2];   // [4096]        fp32
    float* out = (float*)d_out;                  // [8192,4096]   fp32

    cudaFuncSetAttribute(gemm_kernel,
                         cudaFuncAttributeMaxDynamicSharedMemorySize, SMEM_TOTAL);

    quant_kernel<<<(MDIM * 1024) / 256, 256>>>(x, 0);   // -> g_qA, g_sA
    quant_kernel<<<(NDIM * 1024) / 256, 256>>>(W, 1);   // -> g_qB, g_sB
    gemm_kernel<<<(MDIM / BM) * (NDIM / BN), 256, SMEM_TOTAL>>>(bias, out);
}

// round 13
// speedup vs baseline: 3.2802x; 3.2802x over previous
#include <cuda_runtime.h>
#include <cuda_fp16.h>
#include <cuda_fp8.h>
#include <cstdint>

#define KDIM 4096
#define MDIM 8192
#define NDIM 4096

#define BM 128
#define BN 128
#define BK 64
#define STAGES 4
#define KSTEPS (KDIM / BK)    // 64
#define B_OFF 16384
#define STAGE_BYTES 32768
#define SMEM_TOTAL (STAGES * STAGE_BYTES)   // 128 KB

// Dequantized operands in fp16: h = fp16( float(e4m3(v/scale)) * scale )
__device__ __align__(1024) __half g_hA[(size_t)MDIM * KDIM];   // 64 MB
__device__ __align__(1024) __half g_hB[(size_t)NDIM * KDIM];   // 32 MB

// ---------------------------------------------------------------------------
// PTX helpers
// ---------------------------------------------------------------------------
__device__ __forceinline__ uint32_t s2u(const void* p) {
    return (uint32_t)__cvta_generic_to_shared(p);
}
__device__ __forceinline__ void cp16(uint32_t s, const void* g) {
    asm volatile("cp.async.cg.shared.global [%0], [%1], 16;" :: "r"(s), "l"(g) : "memory");
}
__device__ __forceinline__ void cp_commit() {
    asm volatile("cp.async.commit_group;" ::: "memory");
}
__device__ __forceinline__ void cp_wait2() {
    asm volatile("cp.async.wait_group 2;" ::: "memory");
}
__device__ __forceinline__ void ldsm4(uint32_t* r, uint32_t addr) {
    asm volatile("ldmatrix.sync.aligned.m8n8.x4.shared.b16 {%0,%1,%2,%3}, [%4];"
                 : "=r"(r[0]), "=r"(r[1]), "=r"(r[2]), "=r"(r[3]) : "r"(addr));
}
__device__ __forceinline__ void mma16816(float* d, const uint32_t* a,
                                         const uint32_t* b, const float* c) {
    asm volatile(
        "mma.sync.aligned.m16n8k16.row.col.f32.f16.f16.f32 "
        "{%0,%1,%2,%3}, {%4,%5,%6,%7}, {%8,%9}, {%10,%11,%12,%13};"
        : "=f"(d[0]), "=f"(d[1]), "=f"(d[2]), "=f"(d[3])
        : "r"(a[0]), "r"(a[1]), "r"(a[2]), "r"(a[3]), "r"(b[0]), "r"(b[1]),
          "f"(c[0]), "f"(c[1]), "f"(c[2]), "f"(c[3]));
}

// ---------------------------------------------------------------------------
// Quantize + dequantize to fp16. dest selects globals IN DEVICE CODE.
// One thread = 4 consecutive K (float4); 8-lane shuffle amax per 32-group.
// ---------------------------------------------------------------------------
__global__ void quant_kernel(const float* __restrict__ src, int dest) {
    __half* __restrict__ qdst = dest ? g_hB : g_hA;

    long long t = (long long)blockIdx.x * blockDim.x + threadIdx.x;
    long long row = t >> 10;            // 1024 float4 per row
    int f4 = (int)(t & 1023);

    const float4 v4 = reinterpret_cast<const float4*>(src)[t];
    float a = fmaxf(fmaxf(fabsf(v4.x), fabsf(v4.y)),
                    fmaxf(fabsf(v4.z), fabsf(v4.w)));
    a = fmaxf(a, __shfl_xor_sync(0xffffffffu, a, 1));
    a = fmaxf(a, __shfl_xor_sync(0xffffffffu, a, 2));
    a = fmaxf(a, __shfl_xor_sync(0xffffffffu, a, 4));
    float scale = __fdiv_rn(fmaxf(a, 1e-8f), 448.0f);

    float vv[4] = {v4.x, v4.y, v4.z, v4.w};
    __half h[4];
#pragma unroll
    for (int i = 0; i < 4; i++) {
        float q = __fdiv_rn(vv[i], scale);
        __nv_fp8_e4m3 f8(q);                 // RNE, satfinite (matches reference)
        h[i] = __float2half((float)f8 * scale);  // fp16 dequant (adds ~1.6e-4 rms)
    }
    __half2 h01 = __halves2half2(h[0], h[1]);
    __half2 h23 = __halves2half2(h[2], h[3]);
    uint2 st;
    st.x = *reinterpret_cast<uint32_t*>(&h01);
    st.y = *reinterpret_cast<uint32_t*>(&h23);
    *reinterpret_cast<uint2*>(qdst + ((size_t)row << 12) + f4 * 4) = st;
}

// ---------------------------------------------------------------------------
// Plain fp16 GEMM with fp32 accumulate: out = A x B^T + bias
// 128x128 CTA tile, BK=64, 4-stage cp.async, 8 warps (2M x 4N), 64x32 warps.
// MMA chain accumulates directly into acc — no rescale work at all.
// ---------------------------------------------------------------------------
__global__ void __launch_bounds__(256, 1)
gemm_kernel(const float* __restrict__ bias, float* __restrict__ out) {
    extern __shared__ __align__(1024) char smem_raw[];
    const uint32_t sbase = s2u(smem_raw);
    const int tid  = threadIdx.x;
    const int lane = tid & 31;
    const int warp = tid >> 5;
    const int warpM = warp & 1;          // 2 x 64 rows
    const int warpN = warp >> 1;         // 4 x 32 cols

    // Grid swizzle: 16-wide N super-columns
    const int gid = blockIdx.x;
    const int sc  = gid >> 10;
    const int rem = gid & 1023;
    const int blockN = ((sc << 4) | (rem & 15)) * BN;
    const int blockM = (rem >> 4) * BM;

    // ldmatrix lane addressing
    const int lx7   = lane & 7;
    const int aRowB = warpM * 64 + (lane & 15);
    const int aCl   = lane >> 4;
    const int bRowB = warpN * 32 + ((lane >> 4) << 3) + (lane & 7);
    const int bCl   = (lane >> 3) & 1;

    const __half* gA = g_hA + (size_t)blockM * KDIM;
    const __half* gB = g_hB + (size_t)blockN * KDIM;

    float acc[64];
#pragma unroll
    for (int i = 0; i < 64; i++) acc[i] = 0.0f;

    auto load_stage = [&](int stage, int kb) {
        uint32_t st = sbase + stage * STAGE_BYTES;
#pragma unroll
        for (int u = 0; u < 4; u++) {
            int idx = tid + u * 256;           // 0..1023 chunks
            int row = idx >> 3, c = idx & 7;
            cp16(st + row * 128 + (((c ^ (row & 7))) << 4),
                 gA + (size_t)row * KDIM + kb * 64 + c * 8);
        }
#pragma unroll
        for (int u = 0; u < 4; u++) {
            int idx = tid + u * 256;
            int row = idx >> 3, c = idx & 7;
            cp16(st + B_OFF + row * 128 + (((c ^ (row & 7))) << 4),
                 gB + (size_t)row * KDIM + kb * 64 + c * 8);
        }
    };

#pragma unroll
    for (int s = 0; s < 3; s++) { load_stage(s, s); cp_commit(); }

    for (int kb = 0; kb < KSTEPS; kb++) {
        cp_wait2();
        __syncthreads();
        const int stage = kb & 3;
        const uint32_t st = sbase + stage * STAGE_BYTES;

#pragma unroll
        for (int kk = 0; kk < 4; kk++) {       // 4 x k16 slices
            uint32_t afr[4][4], bfr[2][4];
#pragma unroll
            for (int i = 0; i < 4; i++)
                ldsm4(afr[i], st + (aRowB + i * 16) * 128 +
                              (((kk * 2 + aCl) ^ lx7) << 4));
#pragma unroll
            for (int jp = 0; jp < 2; jp++)
                ldsm4(bfr[jp], st + B_OFF + (bRowB + jp * 16) * 128 +
                               (((kk * 2 + bCl) ^ lx7) << 4));
#pragma unroll
            for (int i = 0; i < 4; i++)
#pragma unroll
                for (int j = 0; j < 4; j++) {
                    float* A_ = &acc[((i << 2) + j) << 2];
                    mma16816(A_, afr[i], &bfr[j >> 1][(j & 1) * 2], A_);
                }
        }
        if (kb < KSTEPS - 3) load_stage((kb + 3) & 3, kb + 3);
        cp_commit();   // uniform group count per iteration
    }

    // Epilogue: bias add + fp32 store
#pragma unroll
    for (int i = 0; i < 4; i++) {
        const int r0 = blockM + warpM * 64 + i * 16 + (lane >> 2);
#pragma unroll
        for (int j = 0; j < 4; j++) {
            const int c = blockN + warpN * 32 + j * 8 + ((lane & 3) << 1);
            const float2 bb = __ldg(reinterpret_cast<const float2*>(bias + c));
            const float* A_ = &acc[((i << 2) + j) << 2];
            float2 v0 = {A_[0] + bb.x, A_[1] + bb.y};
            float2 v1 = {A_[2] + bb.x, A_[3] + bb.y};
            *reinterpret_cast<float2*>(out + (size_t)r0 * NDIM + c) = v0;
            *reinterpret_cast<float2*>(out + (size_t)(r0 + 8) * NDIM + c) = v1;
        }
    }
}

// ---------------------------------------------------------------------------
extern "C" void kernel_launch(void* const* d_in, const int* in_sizes, int n_in,
                              void* d_out, int out_size) {
    const float* x    = (const float*)d_in[0];   // [4,2048,4096] fp32
    const float* W    = (const float*)d_in[1];   // [4096,4096]   fp32
    const float* bias = (const float*)d_in[2];   // [4096]        fp32
    float* out = (float*)d_out;                  // [8192,4096]   fp32

    cudaFuncSetAttribute(gemm_kernel,
                         cudaFuncAttributeMaxDynamicSharedMemorySize, SMEM_TOTAL);

    quant_kernel<<<(MDIM * 1024) / 256, 256>>>(x, 0);   // -> g_hA
    quant_kernel<<<(NDIM * 1024) / 256, 256>>>(W, 1);   // -> g_hB
    gemm_kernel<<<(MDIM / BM) * (NDIM / BN), 256, SMEM_TOTAL>>>(bias, out);
}

// round 14
// speedup vs baseline: 3.7951x; 1.1570x over previous
#include <cuda_runtime.h>
#include <cuda_fp16.h>
#include <cuda_fp8.h>
#include <cstdint>

#define KDIM 4096
#define MDIM 8192
#define NDIM 4096

#define BM 128
#define BN 128
#define BK 64
#define STAGES 3
#define KSTEPS (KDIM / BK)    // 64
#define B_OFF 16384
#define STAGE_BYTES 32768
#define SMEM_TOTAL (STAGES * STAGE_BYTES)   // 96 KB -> 2 CTAs/SM

// Dequantized operands in fp16: h = fp16( float(e4m3(v/scale)) * scale )
__device__ __align__(1024) __half g_hA[(size_t)MDIM * KDIM];   // 64 MB
__device__ __align__(1024) __half g_hB[(size_t)NDIM * KDIM];   // 32 MB

// ---------------------------------------------------------------------------
// PTX helpers
// ---------------------------------------------------------------------------
__device__ __forceinline__ uint32_t s2u(const void* p) {
    return (uint32_t)__cvta_generic_to_shared(p);
}
__device__ __forceinline__ void cp16(uint32_t s, const void* g) {
    asm volatile("cp.async.cg.shared.global [%0], [%1], 16;" :: "r"(s), "l"(g) : "memory");
}
__device__ __forceinline__ void cp_commit() {
    asm volatile("cp.async.commit_group;" ::: "memory");
}
__device__ __forceinline__ void cp_wait1() {
    asm volatile("cp.async.wait_group 1;" ::: "memory");
}
__device__ __forceinline__ void ldsm4(uint32_t* r, uint32_t addr) {
    asm volatile("ldmatrix.sync.aligned.m8n8.x4.shared.b16 {%0,%1,%2,%3}, [%4];"
                 : "=r"(r[0]), "=r"(r[1]), "=r"(r[2]), "=r"(r[3]) : "r"(addr));
}
__device__ __forceinline__ void mma16816(float* d, const uint32_t* a,
                                         const uint32_t* b, const float* c) {
    asm volatile(
        "mma.sync.aligned.m16n8k16.row.col.f32.f16.f16.f32 "
        "{%0,%1,%2,%3}, {%4,%5,%6,%7}, {%8,%9}, {%10,%11,%12,%13};"
        : "=f"(d[0]), "=f"(d[1]), "=f"(d[2]), "=f"(d[3])
        : "r"(a[0]), "r"(a[1]), "r"(a[2]), "r"(a[3]), "r"(b[0]), "r"(b[1]),
          "f"(c[0]), "f"(c[1]), "f"(c[2]), "f"(c[3]));
}

// ---------------------------------------------------------------------------
// Fused quantize + dequantize to fp16 for BOTH inputs (one launch).
// Blocks [0, MBLK) handle x -> g_hA; blocks [MBLK, ...) handle W -> g_hB.
// One thread = 4 consecutive K (float4); 8-lane shuffle amax per 32-group.
// ---------------------------------------------------------------------------
#define MBLK ((MDIM * 1024) / 256)

__global__ void quant_kernel(const float* __restrict__ x,
                             const float* __restrict__ W) {
    const int isB = (blockIdx.x >= MBLK);
    const float* __restrict__ src = isB ? W : x;
    __half* __restrict__ qdst = isB ? g_hB : g_hA;
    const int blk = isB ? (blockIdx.x - MBLK) : blockIdx.x;

    long long t = (long long)blk * blockDim.x + threadIdx.x;
    long long row = t >> 10;            // 1024 float4 per row
    int f4 = (int)(t & 1023);

    const float4 v4 = reinterpret_cast<const float4*>(src)[t];
    float a = fmaxf(fmaxf(fabsf(v4.x), fabsf(v4.y)),
                    fmaxf(fabsf(v4.z), fabsf(v4.w)));
    a = fmaxf(a, __shfl_xor_sync(0xffffffffu, a, 1));
    a = fmaxf(a, __shfl_xor_sync(0xffffffffu, a, 2));
    a = fmaxf(a, __shfl_xor_sync(0xffffffffu, a, 4));
    float scale = __fdiv_rn(fmaxf(a, 1e-8f), 448.0f);

    float vv[4] = {v4.x, v4.y, v4.z, v4.w};
    __half h[4];
#pragma unroll
    for (int i = 0; i < 4; i++) {
        float q = __fdiv_rn(vv[i], scale);
        __nv_fp8_e4m3 f8(q);                 // RNE, satfinite (matches reference)
        h[i] = __float2half((float)f8 * scale);  // fp16 dequant
    }
    __half2 h01 = __halves2half2(h[0], h[1]);
    __half2 h23 = __halves2half2(h[2], h[3]);
    uint2 st;
    st.x = *reinterpret_cast<uint32_t*>(&h01);
    st.y = *reinterpret_cast<uint32_t*>(&h23);
    *reinterpret_cast<uint2*>(qdst + ((size_t)row << 12) + f4 * 4) = st;
}

// ---------------------------------------------------------------------------
// Plain fp16 GEMM with fp32 accumulate: out = A x B^T + bias
// 128x128 CTA tile, BK=64, 3-stage cp.async, 8 warps (2M x 4N), 2 CTAs/SM.
// ---------------------------------------------------------------------------
__global__ void __launch_bounds__(256, 2)
gemm_kernel(const float* __restrict__ bias, float* __restrict__ out) {
    extern __shared__ __align__(1024) char smem_raw[];
    const uint32_t sbase = s2u(smem_raw);
    const int tid  = threadIdx.x;
    const int lane = tid & 31;
    const int warp = tid >> 5;
    const int warpM = warp & 1;          // 2 x 64 rows
    const int warpN = warp >> 1;         // 4 x 32 cols

    // Grid swizzle: 16-wide N super-columns
    const int gid = blockIdx.x;
    const int sc  = gid >> 10;
    const int rem = gid & 1023;
    const int blockN = ((sc << 4) | (rem & 15)) * BN;
    const int blockM = (rem >> 4) * BM;

    // ldmatrix lane addressing
    const int lx7   = lane & 7;
    const int aRowB = warpM * 64 + (lane & 15);
    const int aCl   = lane >> 4;
    const int bRowB = warpN * 32 + ((lane >> 4) << 3) + (lane & 7);
    const int bCl   = (lane >> 3) & 1;

    const __half* gA = g_hA + (size_t)blockM * KDIM;
    const __half* gB = g_hB + (size_t)blockN * KDIM;

    float acc[64];
#pragma unroll
    for (int i = 0; i < 64; i++) acc[i] = 0.0f;

    auto load_stage = [&](int stage, int kb) {
        uint32_t st = sbase + stage * STAGE_BYTES;
#pragma unroll
        for (int u = 0; u < 4; u++) {
            int idx = tid + u * 256;           // 0..1023 chunks
            int row = idx >> 3, c = idx & 7;
            cp16(st + row * 128 + (((c ^ (row & 7))) << 4),
                 gA + (size_t)row * KDIM + kb * 64 + c * 8);
        }
#pragma unroll
        for (int u = 0; u < 4; u++) {
            int idx = tid + u * 256;
            int row = idx >> 3, c = idx & 7;
            cp16(st + B_OFF + row * 128 + (((c ^ (row & 7))) << 4),
                 gB + (size_t)row * KDIM + kb * 64 + c * 8);
        }
    };

#pragma unroll
    for (int s = 0; s < 2; s++) { load_stage(s, s); cp_commit(); }

    int stage = 0;
    for (int kb = 0; kb < KSTEPS; kb++) {
        cp_wait1();
        __syncthreads();
        const uint32_t st = sbase + stage * STAGE_BYTES;

#pragma unroll
        for (int kk = 0; kk < 4; kk++) {       // 4 x k16 slices
            uint32_t afr[4][4], bfr[2][4];
#pragma unroll
            for (int i = 0; i < 4; i++)
                ldsm4(afr[i], st + (aRowB + i * 16) * 128 +
                              (((kk * 2 + aCl) ^ lx7) << 4));
#pragma unroll
            for (int jp = 0; jp < 2; jp++)
                ldsm4(bfr[jp], st + B_OFF + (bRowB + jp * 16) * 128 +
                               (((kk * 2 + bCl) ^ lx7) << 4));
#pragma unroll
            for (int i = 0; i < 4; i++)
#pragma unroll
                for (int j = 0; j < 4; j++) {
                    float* A_ = &acc[((i << 2) + j) << 2];
                    mma16816(A_, afr[i], &bfr[j >> 1][(j & 1) * 2], A_);
                }
        }
        // Keep producers 2 iterations ahead (3 buffers)
        if (kb + 2 < KSTEPS) {
            int ns = stage + 2;
            if (ns >= STAGES) ns -= STAGES;
            load_stage(ns, kb + 2);
        }
        cp_commit();   // uniform group count per iteration
        if (++stage == STAGES) stage = 0;
    }

    // Epilogue: bias add + fp32 store
#pragma unroll
    for (int i = 0; i < 4; i++) {
        const int r0 = blockM + warpM * 64 + i * 16 + (lane >> 2);
#pragma unroll
        for (int j = 0; j < 4; j++) {
            const int c = blockN + warpN * 32 + j * 8 + ((lane & 3) << 1);
            const float2 bb = __ldg(reinterpret_cast<const float2*>(bias + c));
            const float* A_ = &acc[((i << 2) + j) << 2];
            float2 v0 = {A_[0] + bb.x, A_[1] + bb.y};
            float2 v1 = {A_[2] + bb.x, A_[3] + bb.y};
            *reinterpret_cast<float2*>(out + (size_t)r0 * NDIM + c) = v0;
            *reinterpret_cast<float2*>(out + (size_t)(r0 + 8) * NDIM + c) = v1;
        }
    }
}

// ---------------------------------------------------------------------------
extern "C" void kernel_launch(void* const* d_in, const int* in_sizes, int n_in,
                              void* d_out, int out_size) {
    const float* x    = (const float*)d_in[0];   // [4,2048,4096] fp32
    const float* W    = (const float*)d_in[1];   // [4096,4096]   fp32
    const float* bias = (const float*)d_in[2];   // [4096]        fp32
    float* out = (float*)d_out;                  // [8192,4096]   fp32

    cudaFuncSetAttribute(gemm_kernel,
                         cudaFuncAttributeMaxDynamicSharedMemorySize, SMEM_TOTAL);

    quant_kernel<<<MBLK + (NDIM * 1024) / 256, 256>>>(x, W);
    gemm_kernel<<<(MDIM / BM) * (NDIM / BN), 256, SMEM_TOTAL>>>(bias, out);
}

// round 15
// speedup vs baseline: 3.9212x; 1.0332x over previous
#include <cuda_runtime.h>
#include <cuda_fp16.h>
#include <cuda_fp8.h>
#include <cstdint>

#define KDIM 4096
#define MDIM 8192
#define NDIM 4096

#define BM 128
#define BN 128
#define BK 64
#define STAGES 3
#define KSTEPS (KDIM / BK)    // 64
#define B_OFF 16384
#define STAGE_BYTES 32768
#define SMEM_TOTAL (STAGES * STAGE_BYTES)   // 96 KB -> 2 CTAs/SM

// Dequantized operands in fp16: h = fp16( float(e4m3(v/scale)) * scale )
__device__ __align__(1024) __half g_hA[(size_t)MDIM * KDIM];   // 64 MB
__device__ __align__(1024) __half g_hB[(size_t)NDIM * KDIM];   // 32 MB

// ---------------------------------------------------------------------------
// PTX helpers
// ---------------------------------------------------------------------------
__device__ __forceinline__ uint32_t s2u(const void* p) {
    return (uint32_t)__cvta_generic_to_shared(p);
}
__device__ __forceinline__ void cp16(uint32_t s, const void* g) {
    asm volatile("cp.async.cg.shared.global [%0], [%1], 16;" :: "r"(s), "l"(g) : "memory");
}
__device__ __forceinline__ void cp_commit() {
    asm volatile("cp.async.commit_group;" ::: "memory");
}
__device__ __forceinline__ void cp_wait1() {
    asm volatile("cp.async.wait_group 1;" ::: "memory");
}
__device__ __forceinline__ void ldsm4(uint32_t* r, uint32_t addr) {
    asm volatile("ldmatrix.sync.aligned.m8n8.x4.shared.b16 {%0,%1,%2,%3}, [%4];"
                 : "=r"(r[0]), "=r"(r[1]), "=r"(r[2]), "=r"(r[3]) : "r"(addr));
}
__device__ __forceinline__ void mma16816(float* d, const uint32_t* a,
                                         const uint32_t* b, const float* c) {
    asm volatile(
        "mma.sync.aligned.m16n8k16.row.col.f32.f16.f16.f32 "
        "{%0,%1,%2,%3}, {%4,%5,%6,%7}, {%8,%9}, {%10,%11,%12,%13};"
        : "=f"(d[0]), "=f"(d[1]), "=f"(d[2]), "=f"(d[3])
        : "r"(a[0]), "r"(a[1]), "r"(a[2]), "r"(a[3]), "r"(b[0]), "r"(b[1]),
          "f"(c[0]), "f"(c[1]), "f"(c[2]), "f"(c[3]));
}

// ---------------------------------------------------------------------------
// Fused quantize + dequantize to fp16 for BOTH inputs (one launch).
// ---------------------------------------------------------------------------
#define MBLK ((MDIM * 1024) / 256)

__global__ void quant_kernel(const float* __restrict__ x,
                             const float* __restrict__ W) {
    const int isB = (blockIdx.x >= MBLK);
    const float* __restrict__ src = isB ? W : x;
    __half* __restrict__ qdst = isB ? g_hB : g_hA;
    const int blk = isB ? (blockIdx.x - MBLK) : blockIdx.x;

    long long t = (long long)blk * blockDim.x + threadIdx.x;
    long long row = t >> 10;            // 1024 float4 per row
    int f4 = (int)(t & 1023);

    const float4 v4 = reinterpret_cast<const float4*>(src)[t];
    float a = fmaxf(fmaxf(fabsf(v4.x), fabsf(v4.y)),
                    fmaxf(fabsf(v4.z), fabsf(v4.w)));
    a = fmaxf(a, __shfl_xor_sync(0xffffffffu, a, 1));
    a = fmaxf(a, __shfl_xor_sync(0xffffffffu, a, 2));
    a = fmaxf(a, __shfl_xor_sync(0xffffffffu, a, 4));
    float scale = __fdiv_rn(fmaxf(a, 1e-8f), 448.0f);

    float vv[4] = {v4.x, v4.y, v4.z, v4.w};
    __half h[4];
#pragma unroll
    for (int i = 0; i < 4; i++) {
        float q = __fdiv_rn(vv[i], scale);
        __nv_fp8_e4m3 f8(q);                 // RNE, satfinite (matches reference)
        h[i] = __float2half((float)f8 * scale);  // fp16 dequant
    }
    __half2 h01 = __halves2half2(h[0], h[1]);
    __half2 h23 = __halves2half2(h[2], h[3]);
    uint2 st;
    st.x = *reinterpret_cast<uint32_t*>(&h01);
    st.y = *reinterpret_cast<uint32_t*>(&h23);
    *reinterpret_cast<uint2*>(qdst + ((size_t)row << 12) + f4 * 4) = st;
}

// ---------------------------------------------------------------------------
// Plain fp16 GEMM with fp32 accumulate: out = A x B^T + bias
// 128x128 CTA tile, BK=64, 3-stage cp.async, 8 warps (2M x 4N), 2 CTAs/SM.
// cp.async chunks interleaved between kk slices; kb loop unrolled x3 so the
// stage index is compile-time.
// ---------------------------------------------------------------------------
__global__ void __launch_bounds__(256, 2)
gemm_kernel(const float* __restrict__ bias, float* __restrict__ out) {
    extern __shared__ __align__(1024) char smem_raw[];
    const uint32_t sbase = s2u(smem_raw);
    const int tid  = threadIdx.x;
    const int lane = tid & 31;
    const int warp = tid >> 5;
    const int warpM = warp & 1;          // 2 x 64 rows
    const int warpN = warp >> 1;         // 4 x 32 cols

    // Grid swizzle: 16-wide N super-columns
    const int gid = blockIdx.x;
    const int sc  = gid >> 10;
    const int rem = gid & 1023;
    const int blockN = ((sc << 4) | (rem & 15)) * BN;
    const int blockM = (rem >> 4) * BM;

    // ldmatrix lane addressing
    const int lx7   = lane & 7;
    const int aRowB = warpM * 64 + (lane & 15);
    const int aCl   = lane >> 4;
    const int bRowB = warpN * 32 + ((lane >> 4) << 3) + (lane & 7);
    const int bCl   = (lane >> 3) & 1;

    const __half* gA = g_hA + (size_t)blockM * KDIM;
    const __half* gB = g_hB + (size_t)blockN * KDIM;

    // Per-thread load addressing (constant across stages)
    const int ldRow = tid >> 3;          // 0..31 base row per 256-chunk group
    const int ldC   = tid & 7;
    const uint32_t sOffA = ldRow * 128 + ((ldC ^ (ldRow & 7)) << 4);

    float acc[64];
#pragma unroll
    for (int i = 0; i < 64; i++) acc[i] = 0.0f;

    // Issue one 1/4 slice of a stage load: chunk u = 32 A-rows + 32 B-rows
    auto load_chunk = [&](int stage, int kb, int u) {
        const uint32_t st = sbase + stage * STAGE_BYTES;
        const int row = ldRow + u * 32;
        const uint32_t so = sOffA + u * 32 * 128;
        cp16(st + so, gA + (size_t)row * KDIM + kb * 64 + ldC * 8);
        cp16(st + B_OFF + so, gB + (size_t)row * KDIM + kb * 64 + ldC * 8);
    };

#pragma unroll
    for (int s = 0; s < 2; s++) {
#pragma unroll
        for (int u = 0; u < 4; u++) load_chunk(s, s, u);
        cp_commit();
    }

#pragma unroll 3
    for (int kb = 0; kb < KSTEPS; kb++) {
        const int stage = kb % STAGES;
        const int pstage = (kb + 2) % STAGES;
        const bool doload = (kb + 2 < KSTEPS);
        cp_wait1();
        __syncthreads();
        const uint32_t st = sbase + stage * STAGE_BYTES;

#pragma unroll
        for (int kk = 0; kk < 4; kk++) {       // 4 x k16 slices
            uint32_t afr[4][4], bfr[2][4];
#pragma unroll
            for (int i = 0; i < 4; i++)
                ldsm4(afr[i], st + (aRowB + i * 16) * 128 +
                              (((kk * 2 + aCl) ^ lx7) << 4));
#pragma unroll
            for (int jp = 0; jp < 2; jp++)
                ldsm4(bfr[jp], st + B_OFF + (bRowB + jp * 16) * 128 +
                               (((kk * 2 + bCl) ^ lx7) << 4));
            // Interleave 1/4 of the prefetch between compute slices
            if (doload) load_chunk(pstage, kb + 2, kk);
#pragma unroll
            for (int i = 0; i < 4; i++)
#pragma unroll
                for (int j = 0; j < 4; j++) {
                    float* A_ = &acc[((i << 2) + j) << 2];
                    mma16816(A_, afr[i], &bfr[j >> 1][(j & 1) * 2], A_);
                }
        }
        cp_commit();   // uniform group count per iteration
    }

    // Epilogue: bias add + fp32 store
#pragma unroll
    for (int i = 0; i < 4; i++) {
        const int r0 = blockM + warpM * 64 + i * 16 + (lane >> 2);
#pragma unroll
        for (int j = 0; j < 4; j++) {
            const int c = blockN + warpN * 32 + j * 8 + ((lane & 3) << 1);
            const float2 bb = __ldg(reinterpret_cast<const float2*>(bias + c));
            const float* A_ = &acc[((i << 2) + j) << 2];
            float2 v0 = {A_[0] + bb.x, A_[1] + bb.y};
            float2 v1 = {A_[2] + bb.x, A_[3] + bb.y};
            *reinterpret_cast<float2*>(out + (size_t)r0 * NDIM + c) = v0;
            *reinterpret_cast<float2*>(out + (size_t)(r0 + 8) * NDIM + c) = v1;
        }
    }
}

// ---------------------------------------------------------------------------
extern "C" void kernel_launch(void* const* d_in, const int* in_sizes, int n_in,
                              void* d_out, int out_size) {
    const float* x    = (const float*)d_in[0];   // [4,2048,4096] fp32
    const float* W    = (const float*)d_in[1];   // [4096,4096]   fp32
    const float* bias = (const float*)d_in[2];   // [4096]        fp32
    float* out = (float*)d_out;                  // [8192,4096]   fp32

    cudaFuncSetAttribute(gemm_kernel,
                         cudaFuncAttributeMaxDynamicSharedMemorySize, SMEM_TOTAL);

    quant_kernel<<<MBLK + (NDIM * 1024) / 256, 256>>>(x, W);
    gemm_kernel<<<(MDIM / BM) * (NDIM / BN), 256, SMEM_TOTAL>>>(bias, out);
}